// round 15
// baseline (speedup 1.0000x reference)
#include <cuda_runtime.h>
#include <math.h>
#include <stdint.h>

#define Bn 32
#define Ln 1024
#define Dn 1024
#define NHn 16
#define HDn 64
#define NCn 64
#define CSn 16
#define In 4096
#define Mn (Bn*Ln)   // 32768 rows

// ---------------- scratch (device globals; no allocation allowed) ----------
__device__ float g_h [(size_t)Mn*Dn];
__device__ float g_q [(size_t)Mn*Dn];
__device__ float g_k [(size_t)Mn*Dn];
__device__ float g_v [(size_t)Mn*Dn];
__device__ float g_to[(size_t)Mn*Dn];
__device__ float g_mlp[(size_t)Mn*In];
__device__ float g_lr [Bn*NHn*Ln];
__device__ float g_wts[12*1024*1024];   // tf32-rounded weights

__device__ __forceinline__ float totf(float x) {
    unsigned r;
    asm("cvt.rna.tf32.f32 %0, %1;" : "=r"(r) : "f"(x));
    return __uint_as_float(r);
}
__device__ __forceinline__ void mma8(float* c, const float* a, const float* b) {
    asm volatile(
        "mma.sync.aligned.m16n8k8.row.col.f32.tf32.tf32.f32 "
        "{%0,%1,%2,%3},{%4,%5,%6,%7},{%8,%9},{%0,%1,%2,%3};"
        : "+f"(c[0]), "+f"(c[1]), "+f"(c[2]), "+f"(c[3])
        : "r"(__float_as_uint(a[0])), "r"(__float_as_uint(a[1])),
          "r"(__float_as_uint(a[2])), "r"(__float_as_uint(a[3])),
          "r"(__float_as_uint(b[0])), "r"(__float_as_uint(b[1])));
}
__device__ __forceinline__ uint32_t smem_u32(const void* p) {
    uint32_t a;
    asm("{ .reg .u64 t; cvta.to.shared.u64 t, %1; cvt.u32.u64 %0, t; }" : "=r"(a) : "l"(p));
    return a;
}
__device__ __forceinline__ void cpa16(uint32_t dst, const void* src) {
    asm volatile("cp.async.cg.shared.global [%0], [%1], 16;" :: "r"(dst), "l"(src));
}
#define CP_COMMIT() asm volatile("cp.async.commit_group;" ::: "memory")
#define CP_WAIT2()  asm volatile("cp.async.wait_group 2;" ::: "memory")
#define CP_WAIT1()  asm volatile("cp.async.wait_group 1;" ::: "memory")
#define CP_WAIT0()  asm volatile("cp.async.wait_group 0;" ::: "memory")

// ---------------- round a float array to tf32 (rna) -------------------------
__global__ void round_kernel(const float* __restrict__ src, float* __restrict__ dst, int n4) {
    int i = blockIdx.x * blockDim.x + threadIdx.x;
    if (i < n4) {
        float4 v = ((const float4*)src)[i];
        ((float4*)dst)[i] = make_float4(totf(v.x), totf(v.y), totf(v.z), totf(v.w));
    }
}

// ============ tf32 GEMM: 128x256 tile, BK=32, cp.async x4 (R13 core) ========
#define ASTR 36
#define BSTR 264
#define AFL (128*ASTR)                 // 4608 floats
#define STAGEF (AFL + 32*BSTR)         // 13056 floats
#define STAGEB (STAGEF*4)              // 52224 bytes
#define GEMM_SMEM (4*STAGEB)           // 208896 bytes (1 CTA/SM)

// FLAGS: 1=BIAS, 2=GELU(exact), 4=RESIDUAL add, 8=HEADED layout, 16=ROUND out
template<int FLAGS>
__global__ void __launch_bounds__(256, 1) gemm_tc(
    const float* __restrict__ A, const float* __restrict__ Bm,
    const float* __restrict__ bias, const float* __restrict__ res,
    float* __restrict__ C, int M, int N, int K)
{
    extern __shared__ float smf[];
    const uint32_t sbase = smem_u32(smf);
    const int t = threadIdx.x, warp = t >> 5, lane = t & 31;
    const int wm = warp >> 2, wn = warp & 3;
    const int gq = lane >> 2, gr = lane & 3;
    const int m0 = blockIdx.y << 7, n0 = blockIdx.x << 8;

    float acc[4][8][4];
#pragma unroll
    for (int mt = 0; mt < 4; mt++)
#pragma unroll
        for (int nt = 0; nt < 8; nt++)
#pragma unroll
            for (int e = 0; e < 4; e++) acc[mt][nt][e] = 0.f;

    const int nslab = K >> 5;

#define STAGE_ISSUE(buf, k0s)                                                        \
    {                                                                                \
        const uint32_t sA = sbase + (uint32_t)(buf) * STAGEB;                        \
        const uint32_t sB = sA + AFL * 4;                                            \
        _Pragma("unroll")                                                            \
        for (int p = 0; p < 4; p++) {                                                \
            int i = t + (p << 8);                                                    \
            int m = i >> 3, kc = (i & 7) << 2;                                       \
            cpa16(sA + (uint32_t)(m * 144 + kc * 4),                                 \
                  A + (size_t)(m0 + m) * K + (k0s) + kc);                            \
        }                                                                            \
        _Pragma("unroll")                                                            \
        for (int p = 0; p < 8; p++) {                                                \
            int i = t + (p << 8);                                                    \
            int k = i >> 6, nc = (i & 63) << 2;                                      \
            cpa16(sB + (uint32_t)(k * 1056 + nc * 4),                                \
                  Bm + (size_t)((k0s) + k) * N + n0 + nc);                           \
        }                                                                            \
        CP_COMMIT();                                                                 \
    }

    STAGE_ISSUE(0, 0)
    if (nslab > 1) STAGE_ISSUE(1, 32)
    if (nslab > 2) STAGE_ISSUE(2, 64)

    for (int s = 0; s < nslab; s++) {
        if (s + 2 < nslab)      { CP_WAIT2(); }
        else if (s + 1 < nslab) { CP_WAIT1(); }
        else                    { CP_WAIT0(); }
        __syncthreads();
        // issue (s+3) immediately: its buffer was drained before this barrier
        if (s + 3 < nslab) STAGE_ISSUE((s + 3) & 3, (s + 3) << 5)
        const float* As = smf + (s & 3) * STAGEF;
        const float* Bs = As + AFL;
#pragma unroll
        for (int kk = 0; kk < 4; kk++) {
            float a[4][4];
            const int ca = (kk << 3) + gr;
#pragma unroll
            for (int mt = 0; mt < 4; mt++) {
                int r = (wm << 6) + (mt << 4) + gq;
                a[mt][0] = As[r * ASTR + ca];
                a[mt][1] = As[(r + 8) * ASTR + ca];
                a[mt][2] = As[r * ASTR + ca + 4];
                a[mt][3] = As[(r + 8) * ASTR + ca + 4];
            }
            float b[8][2];
#pragma unroll
            for (int nt = 0; nt < 8; nt++) {
                int n = (wn << 6) + (nt << 3) + gq;
                b[nt][0] = Bs[ca * BSTR + n];
                b[nt][1] = Bs[(ca + 4) * BSTR + n];
            }
#pragma unroll
            for (int mt = 0; mt < 4; mt++)
#pragma unroll
                for (int nt = 0; nt < 8; nt++)
                    mma8(acc[mt][nt], a[mt], b[nt]);
        }
    }
#undef STAGE_ISSUE

    // ---- epilogue
#pragma unroll
    for (int mt = 0; mt < 4; mt++) {
#pragma unroll
        for (int nt = 0; nt < 8; nt++) {
#pragma unroll
            for (int half = 0; half < 2; half++) {
                int row = m0 + (wm << 6) + (mt << 4) + gq + (half << 3);
                int col = n0 + (wn << 6) + (nt << 3) + (gr << 1);
                float v0 = acc[mt][nt][half * 2 + 0];
                float v1 = acc[mt][nt][half * 2 + 1];
                if (FLAGS & 1) { v0 += bias[col]; v1 += bias[col + 1]; }
                if (FLAGS & 2) {
                    v0 = 0.5f * v0 * (1.f + erff(v0 * 0.70710678118654752f));
                    v1 = 0.5f * v1 * (1.f + erff(v1 * 0.70710678118654752f));
                }
                if (FLAGS & 4) {
                    float2 r2 = *(const float2*)(res + (size_t)row * N + col);
                    v0 += r2.x; v1 += r2.y;
                }
                if (FLAGS & 16) { v0 = totf(v0); v1 = totf(v1); }
                if (FLAGS & 8) {
                    int b = row >> 10, l = row & 1023, hh = col >> 6, hd = col & 63;
                    *(float2*)(C + ((((size_t)((b << 4) + hh) << 10) + l) << 6) + hd)
                        = make_float2(v0, v1);
                } else {
                    *(float2*)(C + (size_t)row * N + col) = make_float2(v0, v1);
                }
            }
        }
    }
}

// ---------------- LayerNorm: one warp per row of 1024 ----------------------
template<int ROUND>
__global__ void ln_kernel(const float* __restrict__ x, const float* __restrict__ w,
                          const float* __restrict__ bb, float* __restrict__ o, float eps) {
    int row  = (blockIdx.x << 3) + (threadIdx.x >> 5);
    int lane = threadIdx.x & 31;
    const float4* xr = (const float4*)(x + (size_t)row * Dn);
    float4 v[8];
    float s = 0.f, s2 = 0.f;
#pragma unroll
    for (int r = 0; r < 8; r++) {
        v[r] = xr[lane + (r << 5)];
        s  += v[r].x + v[r].y + v[r].z + v[r].w;
        s2 += v[r].x*v[r].x + v[r].y*v[r].y + v[r].z*v[r].z + v[r].w*v[r].w;
    }
#pragma unroll
    for (int off = 16; off; off >>= 1) {
        s  += __shfl_xor_sync(0xffffffffu, s,  off);
        s2 += __shfl_xor_sync(0xffffffffu, s2, off);
    }
    float mu  = s * (1.f / 1024.f);
    float var = s2 * (1.f / 1024.f) - mu * mu;
    float rs  = rsqrtf(var + eps);
    const float4* wr = (const float4*)w;
    const float4* br = (const float4*)bb;
    float4* orow = (float4*)(o + (size_t)row * Dn);
#pragma unroll
    for (int r = 0; r < 8; r++) {
        int c = lane + (r << 5);
        float4 W = wr[c], Bv = br[c], X = v[r], O;
        O.x = (X.x - mu) * rs * W.x + Bv.x;
        O.y = (X.y - mu) * rs * W.y + Bv.y;
        O.z = (X.z - mu) * rs * W.z + Bv.z;
        O.w = (X.w - mu) * rs * W.w + Bv.w;
        if (ROUND) { O.x = totf(O.x); O.y = totf(O.y); O.z = totf(O.z); O.w = totf(O.w); }
        orow[c] = O;
    }
}

// ---------------- ttt_lr = sigmoid(h . lr_w[h] + lr_b[h]) / HD -------------
__global__ void lr_kernel(const float* __restrict__ lrw, const float* __restrict__ lrb) {
    __shared__ float hs[1024];
    int m = blockIdx.x, t = threadIdx.x;
    ((float4*)hs)[t] = ((const float4*)(g_h + (size_t)m * Dn))[t];
    __syncthreads();
    int w = t >> 5, lane = t & 31;
    for (int hh = w; hh < NHn; hh += 8) {
        const float* lw = lrw + hh * Dn;
        float s = 0.f;
#pragma unroll
        for (int r = 0; r < 32; r++) s += hs[lane + (r << 5)] * lw[lane + (r << 5)];
#pragma unroll
        for (int off = 16; off; off >>= 1) s += __shfl_xor_sync(0xffffffffu, s, off);
        if (lane == 0) {
            float val = (1.f / (1.f + expf(-(s + lrb[hh])))) * (1.f / 64.f);
            int b = m >> 10, l = m & 1023;
            g_lr[(((b << 4) + hh) << 10) + l] = val;
        }
    }
}

// ---------------- TTT inner scan: one block per (b,h), W1/b1 in smem -------
// 5 barriers/chunk: load / Z1+Attn / grad / Z1_bar / W1upd+outLN
__global__ void __launch_bounds__(256) ttt_scan_kernel(
    const float* __restrict__ W1i, const float* __restrict__ b1i,
    const float* __restrict__ nw,  const float* __restrict__ nb,
    const float* __restrict__ tokp)
{
    __shared__ float W1[4096];
    __shared__ float b1[64], gam[64], bet[64];
    __shared__ float tki[16], lrs[16];
    __shared__ float xq[1024], xk[1024], xv[1024];
    __shared__ float Zb[1024];
    __shared__ float G[1024];
    __shared__ float At[256];

    const int bx = blockIdx.x;
    const int b = bx >> 4, h = bx & 15;
    const int t = threadIdx.x;

    {
        const float* w0 = W1i + h * 4096;
        for (int r = t; r < 4096; r += 256) W1[r] = w0[r];
        if (t < 64) {
            b1[t]  = b1i[(h << 6) + t];
            gam[t] = nw [(h << 6) + t];
            bet[t] = nb [(h << 6) + t];
        }
        if (t < 16) tki[t] = fmaxf(1.f / (float)(t + 1) + tokp[t], 0.f);
    }
    const float4* qb = (const float4*)(g_q + (size_t)bx * Ln * HDn);
    const float4* kb = (const float4*)(g_k + (size_t)bx * Ln * HDn);
    const float4* vb = (const float4*)(g_v + (size_t)bx * Ln * HDn);
    const float*  lrg = g_lr + (size_t)bx * Ln;
    __syncthreads();

    const int d = t & 63, g = t >> 6;
    const int wp = t >> 5, lane = t & 31;
    const int i0 = g << 2;

    for (int nc = 0; nc < NCn; nc++) {
        ((float4*)xq)[t] = qb[nc * 256 + t];
        ((float4*)xk)[t] = kb[nc * 256 + t];
        ((float4*)xv)[t] = vb[nc * 256 + t];
        if (t < 16) lrs[t] = lrg[(nc << 4) + t];
        __syncthreads();

        // ---- Z1 = xk@W1 + b1  AND  Attn = tril(xq @ xk^T)
        {
            float a0 = b1[d], a1 = a0, a2 = a0, a3 = a0;
#pragma unroll
            for (int k4 = 0; k4 < 64; k4 += 4) {
                float4 x0 = *(const float4*)&xk[(i0 + 0) * 64 + k4];
                float4 x1 = *(const float4*)&xk[(i0 + 1) * 64 + k4];
                float4 x2 = *(const float4*)&xk[(i0 + 2) * 64 + k4];
                float4 x3 = *(const float4*)&xk[(i0 + 3) * 64 + k4];
                float w0 = W1[(k4 + 0) * 64 + d], w1 = W1[(k4 + 1) * 64 + d];
                float w2 = W1[(k4 + 2) * 64 + d], w3 = W1[(k4 + 3) * 64 + d];
                a0 += x0.x * w0 + x0.y * w1 + x0.z * w2 + x0.w * w3;
                a1 += x1.x * w0 + x1.y * w1 + x1.z * w2 + x1.w * w3;
                a2 += x2.x * w0 + x2.y * w1 + x2.z * w2 + x2.w * w3;
                a3 += x3.x * w0 + x3.y * w1 + x3.z * w2 + x3.w * w3;
            }
            Zb[(i0 + 0) * 64 + d] = a0; Zb[(i0 + 1) * 64 + d] = a1;
            Zb[(i0 + 2) * 64 + d] = a2; Zb[(i0 + 3) * 64 + d] = a3;

            int i = t >> 4, j = t & 15;
            float s = 0.f;
            if (j <= i) {
#pragma unroll
                for (int k = 0; k < 64; k += 4) {
                    float4 a = *(const float4*)&xq[i * 64 + k];
                    float4 c = *(const float4*)&xk[j * 64 + k];
                    s += a.x * c.x + a.y * c.y + a.z * c.z + a.w * c.w;
                }
            }
            At[t] = s;
        }
        __syncthreads();

        // ---- grad = ln_fused_l2_bwd
        {
#pragma unroll
            for (int rr = 0; rr < 2; rr++) {
                int i = (wp << 1) + rr;
                float z0 = Zb[i * 64 + lane], z1 = Zb[i * 64 + lane + 32];
                float s = z0 + z1, s2 = z0 * z0 + z1 * z1;
#pragma unroll
                for (int off = 16; off; off >>= 1) {
                    s  += __shfl_xor_sync(0xffffffffu, s,  off);
                    s2 += __shfl_xor_sync(0xffffffffu, s2, off);
                }
                float mu = s * (1.f / 64.f);
                float var = s2 * (1.f / 64.f) - mu * mu;
                float std = sqrtf(var + 1e-6f);
                float rstd = 1.f / std;
                float xh0 = (z0 - mu) * rstd, xh1 = (z1 - mu) * rstd;
                float g0 = gam[lane], g1 = gam[lane + 32];
                float gx0 = (g0 * xh0 + bet[lane]      - (xv[i * 64 + lane]      - xk[i * 64 + lane]))      * g0;
                float gx1 = (g1 * xh1 + bet[lane + 32] - (xv[i * 64 + lane + 32] - xk[i * 64 + lane + 32])) * g1;
                float sg = gx0 + gx1, sx = gx0 * xh0 + gx1 * xh1;
#pragma unroll
                for (int off = 16; off; off >>= 1) {
                    sg += __shfl_xor_sync(0xffffffffu, sg, off);
                    sx += __shfl_xor_sync(0xffffffffu, sx, off);
                }
                float cc = 1.f / (64.f * std);
                G[i * 64 + lane]      = (64.f * gx0 - sg - xh0 * sx) * cc;
                G[i * 64 + lane + 32] = (64.f * gx1 - sg - xh1 * sx) * cc;
            }
        }
        __syncthreads();

        // ---- Z1_bar
        {
            float ti0 = tki[i0], ti1 = tki[i0 + 1], ti2 = tki[i0 + 2], ti3 = tki[i0 + 3];
            float a0 = b1[d], a1 = a0, a2 = a0, a3 = a0;
#pragma unroll
            for (int j = 0; j < 16; j++) {
                float bbx = lrs[j] * G[j * 64 + d];
                if (j <= i0)     a0 -= ti0 * bbx * (1.f + At[(i0 + 0) * 16 + j]);
                if (j <= i0 + 1) a1 -= ti1 * bbx * (1.f + At[(i0 + 1) * 16 + j]);
                if (j <= i0 + 2) a2 -= ti2 * bbx * (1.f + At[(i0 + 2) * 16 + j]);
                if (j <= i0 + 3) a3 -= ti3 * bbx * (1.f + At[(i0 + 3) * 16 + j]);
            }
#pragma unroll
            for (int k4 = 0; k4 < 64; k4 += 4) {
                float4 x0 = *(const float4*)&xq[(i0 + 0) * 64 + k4];
                float4 x1 = *(const float4*)&xq[(i0 + 1) * 64 + k4];
                float4 x2 = *(const float4*)&xq[(i0 + 2) * 64 + k4];
                float4 x3 = *(const float4*)&xq[(i0 + 3) * 64 + k4];
                float w0 = W1[(k4 + 0) * 64 + d], w1 = W1[(k4 + 1) * 64 + d];
                float w2 = W1[(k4 + 2) * 64 + d], w3 = W1[(k4 + 3) * 64 + d];
                a0 += x0.x * w0 + x0.y * w1 + x0.z * w2 + x0.w * w3;
                a1 += x1.x * w0 + x1.y * w1 + x1.z * w2 + x1.w * w3;
                a2 += x2.x * w0 + x2.y * w1 + x2.z * w2 + x2.w * w3;
                a3 += x3.x * w0 + x3.y * w1 + x3.z * w2 + x3.w * w3;
            }
            Zb[(i0 + 0) * 64 + d] = a0; Zb[(i0 + 1) * 64 + d] = a1;
            Zb[(i0 + 2) * 64 + d] = a2; Zb[(i0 + 3) * 64 + d] = a3;
        }
        __syncthreads();

        // ---- W1/b1 update  AND  out = xq + LN(Z1_bar)
        {
            float te = tki[15];
            float ge[16];
#pragma unroll
            for (int k = 0; k < 16; k++) ge[k] = lrs[k] * G[k * 64 + d];
            float acc[16];
#pragma unroll
            for (int s_ = 0; s_ < 16; s_++) acc[s_] = 0.f;
#pragma unroll
            for (int k = 0; k < 16; k++) {
                const float4* xr = (const float4*)&xk[k * 64 + (g << 4)];
                float4 x0 = xr[0], x1 = xr[1], x2 = xr[2], x3 = xr[3];
                float gg = ge[k];
                acc[0]  += x0.x * gg; acc[1]  += x0.y * gg; acc[2]  += x0.z * gg; acc[3]  += x0.w * gg;
                acc[4]  += x1.x * gg; acc[5]  += x1.y * gg; acc[6]  += x1.z * gg; acc[7]  += x1.w * gg;
                acc[8]  += x2.x * gg; acc[9]  += x2.y * gg; acc[10] += x2.z * gg; acc[11] += x2.w * gg;
                acc[12] += x3.x * gg; acc[13] += x3.y * gg; acc[14] += x3.z * gg; acc[15] += x3.w * gg;
            }
#pragma unroll
            for (int s_ = 0; s_ < 16; s_++) {
                int dd = (g << 4) + s_;
                W1[dd * 64 + d] -= te * acc[s_];
            }
            if (g == 0) {
                float sb = 0.f;
#pragma unroll
                for (int k = 0; k < 16; k++) sb += ge[k];
                b1[d] -= te * sb;
            }

#pragma unroll
            for (int rr = 0; rr < 2; rr++) {
                int i = (wp << 1) + rr;
                float z0 = Zb[i * 64 + lane], z1 = Zb[i * 64 + lane + 32];
                float s = z0 + z1, s2 = z0 * z0 + z1 * z1;
#pragma unroll
                for (int off = 16; off; off >>= 1) {
                    s  += __shfl_xor_sync(0xffffffffu, s,  off);
                    s2 += __shfl_xor_sync(0xffffffffu, s2, off);
                }
                float mu = s * (1.f / 64.f);
                float var = s2 * (1.f / 64.f) - mu * mu;
                float rs = rsqrtf(var + 1e-6f);
                float o0 = xq[i * 64 + lane]      + (z0 - mu) * rs * gam[lane]      + bet[lane];
                float o1 = xq[i * 64 + lane + 32] + (z1 - mu) * rs * gam[lane + 32] + bet[lane + 32];
                size_t row = (size_t)(b << 10) + (nc << 4) + i;
                g_to[row * 1024 + (h << 6) + lane]      = o0;
                g_to[row * 1024 + (h << 6) + lane + 32] = o1;
            }
        }
        __syncthreads();
    }
}

// ---------------- launch ----------------------------------------------------
extern "C" void kernel_launch(void* const* d_in, const int* in_sizes, int n_in,
                              void* d_out, int out_size) {
    (void)in_sizes; (void)n_in; (void)out_size;
    const float* x    = (const float*)d_in[0];
    const float* ln1w = (const float*)d_in[2];
    const float* ln1b = (const float*)d_in[3];
    const float* wq   = (const float*)d_in[4];
    const float* wk   = (const float*)d_in[5];
    const float* wv   = (const float*)d_in[6];
    const float* wo   = (const float*)d_in[7];
    const float* W1i  = (const float*)d_in[8];
    const float* b1i  = (const float*)d_in[9];
    const float* nw   = (const float*)d_in[10];
    const float* nb   = (const float*)d_in[11];
    const float* lrw  = (const float*)d_in[12];
    const float* lrb  = (const float*)d_in[13];
    const float* tokp = (const float*)d_in[14];
    const float* pnw  = (const float*)d_in[15];
    const float* pnb  = (const float*)d_in[16];
    const float* ln2w = (const float*)d_in[17];
    const float* ln2b = (const float*)d_in[18];
    const float* win  = (const float*)d_in[19];
    const float* bin  = (const float*)d_in[20];
    const float* wout = (const float*)d_in[21];
    const float* bout = (const float*)d_in[22];
    float* out = (float*)d_out;

    float *ph, *pq, *pk, *pv, *pt, *pm, *pw;
    cudaGetSymbolAddress((void**)&ph, g_h);
    cudaGetSymbolAddress((void**)&pq, g_q);
    cudaGetSymbolAddress((void**)&pk, g_k);
    cudaGetSymbolAddress((void**)&pv, g_v);
    cudaGetSymbolAddress((void**)&pt, g_to);
    cudaGetSymbolAddress((void**)&pm, g_mlp);
    cudaGetSymbolAddress((void**)&pw, g_wts);

    float* rwq = pw;
    float* rwk = pw + 1u*1024*1024;
    float* rwv = pw + 2u*1024*1024;
    float* rwo = pw + 3u*1024*1024;
    float* rwi = pw + 4u*1024*1024;
    float* rwu = pw + 8u*1024*1024;

    cudaFuncSetAttribute(gemm_tc<8>,  cudaFuncAttributeMaxDynamicSharedMemorySize, GEMM_SMEM);
    cudaFuncSetAttribute(gemm_tc<4>,  cudaFuncAttributeMaxDynamicSharedMemorySize, GEMM_SMEM);
    cudaFuncSetAttribute(gemm_tc<19>, cudaFuncAttributeMaxDynamicSharedMemorySize, GEMM_SMEM);
    cudaFuncSetAttribute(gemm_tc<5>,  cudaFuncAttributeMaxDynamicSharedMemorySize, GEMM_SMEM);

    dim3 g1(Dn / 256, Mn / 128);   // (4, 256)
    dim3 g2(In / 256, Mn / 128);   // (16, 256)

    // #1 h = LN(x) (rounded)
    ln_kernel<1><<<Mn / 8, 256>>>(x, ln1w, ln1b, ph, 1e-5f);
    // #2 ttt_lr
    lr_kernel<<<Mn, 256>>>(lrw, lrb);
    // #3 round wq
    round_kernel<<<1024, 256>>>(wq, rwq, 1024*1024/4);
    // #4 XQ gemm (profiled slot)
    gemm_tc<8><<<g1, 256, GEMM_SMEM>>>(ph, rwq, nullptr, nullptr, pq, Mn, Dn, Dn);
    round_kernel<<<1024, 256>>>(wk, rwk, 1024*1024/4);
    gemm_tc<8><<<g1, 256, GEMM_SMEM>>>(ph, rwk, nullptr, nullptr, pk, Mn, Dn, Dn);
    round_kernel<<<1024, 256>>>(wv, rwv, 1024*1024/4);
    gemm_tc<8><<<g1, 256, GEMM_SMEM>>>(ph, rwv, nullptr, nullptr, pv, Mn, Dn, Dn);
    round_kernel<<<1024, 256>>>(wo,   rwo, 1024*1024/4);
    round_kernel<<<4096, 256>>>(win,  rwi, 4*1024*1024/4);
    round_kernel<<<4096, 256>>>(wout, rwu, 4*1024*1024/4);
    ttt_scan_kernel<<<Bn * NHn, 256>>>(W1i, b1i, nw, nb, tokp);
    ln_kernel<1><<<Mn / 8, 256>>>(pt, pnw, pnb, ph, 1e-5f);
    gemm_tc<4><<<g1, 256, GEMM_SMEM>>>(ph, rwo, nullptr, x, pq, Mn, Dn, Dn);
    ln_kernel<1><<<Mn / 8, 256>>>(pq, ln2w, ln2b, pk, 1e-5f);
    gemm_tc<19><<<g2, 256, GEMM_SMEM>>>(pk, rwi, bin, nullptr, pm, Mn, In, Dn);
    gemm_tc<5><<<g1, 256, GEMM_SMEM>>>(pm, rwu, bout, pq, out, Mn, Dn, In);
}

// round 16
// speedup vs baseline: 1.0718x; 1.0718x over previous
#include <cuda_runtime.h>
#include <math.h>
#include <stdint.h>

#define Bn 32
#define Ln 1024
#define Dn 1024
#define NHn 16
#define HDn 64
#define NCn 64
#define CSn 16
#define In 4096
#define Mn (Bn*Ln)   // 32768 rows

// ---------------- scratch (device globals; no allocation allowed) ----------
__device__ float g_h [(size_t)Mn*Dn];
__device__ float g_q [(size_t)Mn*Dn];
__device__ float g_k [(size_t)Mn*Dn];
__device__ float g_v [(size_t)Mn*Dn];
__device__ float g_to[(size_t)Mn*Dn];
__device__ float g_mlp[(size_t)Mn*In];
__device__ float g_lr [Bn*NHn*Ln];
__device__ float g_wts[12*1024*1024];   // tf32-rounded weights

__device__ __forceinline__ float totf(float x) {
    unsigned r;
    asm("cvt.rna.tf32.f32 %0, %1;" : "=r"(r) : "f"(x));
    return __uint_as_float(r);
}
__device__ __forceinline__ void mma8(float* c, const float* a, const float* b) {
    asm volatile(
        "mma.sync.aligned.m16n8k8.row.col.f32.tf32.tf32.f32 "
        "{%0,%1,%2,%3},{%4,%5,%6,%7},{%8,%9},{%0,%1,%2,%3};"
        : "+f"(c[0]), "+f"(c[1]), "+f"(c[2]), "+f"(c[3])
        : "r"(__float_as_uint(a[0])), "r"(__float_as_uint(a[1])),
          "r"(__float_as_uint(a[2])), "r"(__float_as_uint(a[3])),
          "r"(__float_as_uint(b[0])), "r"(__float_as_uint(b[1])));
}
__device__ __forceinline__ uint32_t smem_u32(const void* p) {
    uint32_t a;
    asm("{ .reg .u64 t; cvta.to.shared.u64 t, %1; cvt.u32.u64 %0, t; }" : "=r"(a) : "l"(p));
    return a;
}
__device__ __forceinline__ void cpa16(uint32_t dst, const void* src) {
    asm volatile("cp.async.cg.shared.global [%0], [%1], 16;" :: "r"(dst), "l"(src));
}
#define CP_COMMIT() asm volatile("cp.async.commit_group;" ::: "memory")
#define CP_WAIT2()  asm volatile("cp.async.wait_group 2;" ::: "memory")
#define CP_WAIT1()  asm volatile("cp.async.wait_group 1;" ::: "memory")
#define CP_WAIT0()  asm volatile("cp.async.wait_group 0;" ::: "memory")

// ---------------- round a float array to tf32 (rna) -------------------------
__global__ void round_kernel(const float* __restrict__ src, float* __restrict__ dst, int n4) {
    int i = blockIdx.x * blockDim.x + threadIdx.x;
    if (i < n4) {
        float4 v = ((const float4*)src)[i];
        ((float4*)dst)[i] = make_float4(totf(v.x), totf(v.y), totf(v.z), totf(v.w));
    }
}

// ============ tf32 GEMM: 128x256 tile, BK=32, cp.async x4 (R13 core) ========
#define ASTR 36
#define BSTR 264
#define AFL (128*ASTR)                 // 4608 floats
#define STAGEF (AFL + 32*BSTR)         // 13056 floats
#define STAGEB (STAGEF*4)              // 52224 bytes
#define GEMM_SMEM (4*STAGEB)           // 208896 bytes (1 CTA/SM)

// FLAGS: 1=BIAS, 2=GELU(exact), 4=RESIDUAL add, 8=HEADED layout, 16=ROUND out
template<int FLAGS>
__global__ void __launch_bounds__(256, 1) gemm_tc(
    const float* __restrict__ A, const float* __restrict__ Bm,
    const float* __restrict__ bias, const float* __restrict__ res,
    float* __restrict__ C, int M, int N, int K)
{
    extern __shared__ float smf[];
    const uint32_t sbase = smem_u32(smf);
    const int t = threadIdx.x, warp = t >> 5, lane = t & 31;
    const int wm = warp >> 2, wn = warp & 3;
    const int gq = lane >> 2, gr = lane & 3;
    const int m0 = blockIdx.y << 7, n0 = blockIdx.x << 8;

    float acc[4][8][4];
#pragma unroll
    for (int mt = 0; mt < 4; mt++)
#pragma unroll
        for (int nt = 0; nt < 8; nt++)
#pragma unroll
            for (int e = 0; e < 4; e++) acc[mt][nt][e] = 0.f;

    const int nslab = K >> 5;

#define STAGE_ISSUE(buf, k0s)                                                        \
    {                                                                                \
        const uint32_t sA = sbase + (uint32_t)(buf) * STAGEB;                        \
        const uint32_t sB = sA + AFL * 4;                                            \
        _Pragma("unroll")                                                            \
        for (int p = 0; p < 4; p++) {                                                \
            int i = t + (p << 8);                                                    \
            int m = i >> 3, kc = (i & 7) << 2;                                       \
            cpa16(sA + (uint32_t)(m * 144 + kc * 4),                                 \
                  A + (size_t)(m0 + m) * K + (k0s) + kc);                            \
        }                                                                            \
        _Pragma("unroll")                                                            \
        for (int p = 0; p < 8; p++) {                                                \
            int i = t + (p << 8);                                                    \
            int k = i >> 6, nc = (i & 63) << 2;                                      \
            cpa16(sB + (uint32_t)(k * 1056 + nc * 4),                                \
                  Bm + (size_t)((k0s) + k) * N + n0 + nc);                           \
        }                                                                            \
        CP_COMMIT();                                                                 \
    }

    STAGE_ISSUE(0, 0)
    if (nslab > 1) STAGE_ISSUE(1, 32)
    if (nslab > 2) STAGE_ISSUE(2, 64)

    for (int s = 0; s < nslab; s++) {
        if (s + 2 < nslab)      { CP_WAIT2(); }
        else if (s + 1 < nslab) { CP_WAIT1(); }
        else                    { CP_WAIT0(); }
        __syncthreads();
        const float* As = smf + (s & 3) * STAGEF;
        const float* Bs = As + AFL;
#pragma unroll
        for (int kk = 0; kk < 4; kk++) {
            float a[4][4];
            const int ca = (kk << 3) + gr;
#pragma unroll
            for (int mt = 0; mt < 4; mt++) {
                int r = (wm << 6) + (mt << 4) + gq;
                a[mt][0] = As[r * ASTR + ca];
                a[mt][1] = As[(r + 8) * ASTR + ca];
                a[mt][2] = As[r * ASTR + ca + 4];
                a[mt][3] = As[(r + 8) * ASTR + ca + 4];
            }
            float b[8][2];
#pragma unroll
            for (int nt = 0; nt < 8; nt++) {
                int n = (wn << 6) + (nt << 3) + gq;
                b[nt][0] = Bs[ca * BSTR + n];
                b[nt][1] = Bs[(ca + 4) * BSTR + n];
            }
#pragma unroll
            for (int mt = 0; mt < 4; mt++)
#pragma unroll
                for (int nt = 0; nt < 8; nt++)
                    mma8(acc[mt][nt], a[mt], b[nt]);
        }
        if (s + 3 < nslab) STAGE_ISSUE((s + 3) & 3, (s + 3) << 5)
    }
#undef STAGE_ISSUE

    // ---- epilogue
#pragma unroll
    for (int mt = 0; mt < 4; mt++) {
#pragma unroll
        for (int nt = 0; nt < 8; nt++) {
#pragma unroll
            for (int half = 0; half < 2; half++) {
                int row = m0 + (wm << 6) + (mt << 4) + gq + (half << 3);
                int col = n0 + (wn << 6) + (nt << 3) + (gr << 1);
                float v0 = acc[mt][nt][half * 2 + 0];
                float v1 = acc[mt][nt][half * 2 + 1];
                if (FLAGS & 1) { v0 += bias[col]; v1 += bias[col + 1]; }
                if (FLAGS & 2) {
                    v0 = 0.5f * v0 * (1.f + erff(v0 * 0.70710678118654752f));
                    v1 = 0.5f * v1 * (1.f + erff(v1 * 0.70710678118654752f));
                }
                if (FLAGS & 4) {
                    float2 r2 = *(const float2*)(res + (size_t)row * N + col);
                    v0 += r2.x; v1 += r2.y;
                }
                if (FLAGS & 16) { v0 = totf(v0); v1 = totf(v1); }
                if (FLAGS & 8) {
                    int b = row >> 10, l = row & 1023, hh = col >> 6, hd = col & 63;
                    *(float2*)(C + ((((size_t)((b << 4) + hh) << 10) + l) << 6) + hd)
                        = make_float2(v0, v1);
                } else {
                    *(float2*)(C + (size_t)row * N + col) = make_float2(v0, v1);
                }
            }
        }
    }
}

// ---------------- LayerNorm: one warp per row of 1024 ----------------------
template<int ROUND>
__global__ void ln_kernel(const float* __restrict__ x, const float* __restrict__ w,
                          const float* __restrict__ bb, float* __restrict__ o, float eps) {
    int row  = (blockIdx.x << 3) + (threadIdx.x >> 5);
    int lane = threadIdx.x & 31;
    const float4* xr = (const float4*)(x + (size_t)row * Dn);
    float4 v[8];
    float s = 0.f, s2 = 0.f;
#pragma unroll
    for (int r = 0; r < 8; r++) {
        v[r] = xr[lane + (r << 5)];
        s  += v[r].x + v[r].y + v[r].z + v[r].w;
        s2 += v[r].x*v[r].x + v[r].y*v[r].y + v[r].z*v[r].z + v[r].w*v[r].w;
    }
#pragma unroll
    for (int off = 16; off; off >>= 1) {
        s  += __shfl_xor_sync(0xffffffffu, s,  off);
        s2 += __shfl_xor_sync(0xffffffffu, s2, off);
    }
    float mu  = s * (1.f / 1024.f);
    float var = s2 * (1.f / 1024.f) - mu * mu;
    float rs  = rsqrtf(var + eps);
    const float4* wr = (const float4*)w;
    const float4* br = (const float4*)bb;
    float4* orow = (float4*)(o + (size_t)row * Dn);
#pragma unroll
    for (int r = 0; r < 8; r++) {
        int c = lane + (r << 5);
        float4 W = wr[c], Bv = br[c], X = v[r], O;
        O.x = (X.x - mu) * rs * W.x + Bv.x;
        O.y = (X.y - mu) * rs * W.y + Bv.y;
        O.z = (X.z - mu) * rs * W.z + Bv.z;
        O.w = (X.w - mu) * rs * W.w + Bv.w;
        if (ROUND) { O.x = totf(O.x); O.y = totf(O.y); O.z = totf(O.z); O.w = totf(O.w); }
        orow[c] = O;
    }
}

// ---------------- ttt_lr = sigmoid(h . lr_w[h] + lr_b[h]) / HD -------------
__global__ void lr_kernel(const float* __restrict__ lrw, const float* __restrict__ lrb) {
    __shared__ float hs[1024];
    int m = blockIdx.x, t = threadIdx.x;
    ((float4*)hs)[t] = ((const float4*)(g_h + (size_t)m * Dn))[t];
    __syncthreads();
    int w = t >> 5, lane = t & 31;
    for (int hh = w; hh < NHn; hh += 8) {
        const float* lw = lrw + hh * Dn;
        float s = 0.f;
#pragma unroll
        for (int r = 0; r < 32; r++) s += hs[lane + (r << 5)] * lw[lane + (r << 5)];
#pragma unroll
        for (int off = 16; off; off >>= 1) s += __shfl_xor_sync(0xffffffffu, s, off);
        if (lane == 0) {
            float val = (1.f / (1.f + expf(-(s + lrb[hh])))) * (1.f / 64.f);
            int b = m >> 10, l = m & 1023;
            g_lr[(((b << 4) + hh) << 10) + l] = val;
        }
    }
}

// ---------------- TTT inner scan: one block per (b,h), W1/b1 in smem -------
// 5 barriers/chunk: load / Z1+Attn / grad / Z1_bar / W1upd+outLN
__global__ void __launch_bounds__(256) ttt_scan_kernel(
    const float* __restrict__ W1i, const float* __restrict__ b1i,
    const float* __restrict__ nw,  const float* __restrict__ nb,
    const float* __restrict__ tokp)
{
    __shared__ float W1[4096];
    __shared__ float b1[64], gam[64], bet[64];
    __shared__ float tki[16], lrs[16];
    __shared__ float xq[1024], xk[1024], xv[1024];
    __shared__ float Zb[1024];
    __shared__ float G[1024];
    __shared__ float At[256];

    const int bx = blockIdx.x;
    const int b = bx >> 4, h = bx & 15;
    const int t = threadIdx.x;

    {
        const float* w0 = W1i + h * 4096;
        for (int r = t; r < 4096; r += 256) W1[r] = w0[r];
        if (t < 64) {
            b1[t]  = b1i[(h << 6) + t];
            gam[t] = nw [(h << 6) + t];
            bet[t] = nb [(h << 6) + t];
        }
        if (t < 16) tki[t] = fmaxf(1.f / (float)(t + 1) + tokp[t], 0.f);
    }
    const float4* qb = (const float4*)(g_q + (size_t)bx * Ln * HDn);
    const float4* kb = (const float4*)(g_k + (size_t)bx * Ln * HDn);
    const float4* vb = (const float4*)(g_v + (size_t)bx * Ln * HDn);
    const float*  lrg = g_lr + (size_t)bx * Ln;
    __syncthreads();

    const int d = t & 63, g = t >> 6;
    const int wp = t >> 5, lane = t & 31;
    const int i0 = g << 2;

    for (int nc = 0; nc < NCn; nc++) {
        ((float4*)xq)[t] = qb[nc * 256 + t];
        ((float4*)xk)[t] = kb[nc * 256 + t];
        ((float4*)xv)[t] = vb[nc * 256 + t];
        if (t < 16) lrs[t] = lrg[(nc << 4) + t];
        __syncthreads();

        // ---- Z1 = xk@W1 + b1  AND  Attn = tril(xq @ xk^T)
        {
            float a0 = b1[d], a1 = a0, a2 = a0, a3 = a0;
#pragma unroll
            for (int k4 = 0; k4 < 64; k4 += 4) {
                float4 x0 = *(const float4*)&xk[(i0 + 0) * 64 + k4];
                float4 x1 = *(const float4*)&xk[(i0 + 1) * 64 + k4];
                float4 x2 = *(const float4*)&xk[(i0 + 2) * 64 + k4];
                float4 x3 = *(const float4*)&xk[(i0 + 3) * 64 + k4];
                float w0 = W1[(k4 + 0) * 64 + d], w1 = W1[(k4 + 1) * 64 + d];
                float w2 = W1[(k4 + 2) * 64 + d], w3 = W1[(k4 + 3) * 64 + d];
                a0 += x0.x * w0 + x0.y * w1 + x0.z * w2 + x0.w * w3;
                a1 += x1.x * w0 + x1.y * w1 + x1.z * w2 + x1.w * w3;
                a2 += x2.x * w0 + x2.y * w1 + x2.z * w2 + x2.w * w3;
                a3 += x3.x * w0 + x3.y * w1 + x3.z * w2 + x3.w * w3;
            }
            Zb[(i0 + 0) * 64 + d] = a0; Zb[(i0 + 1) * 64 + d] = a1;
            Zb[(i0 + 2) * 64 + d] = a2; Zb[(i0 + 3) * 64 + d] = a3;

            int i = t >> 4, j = t & 15;
            float s = 0.f;
            if (j <= i) {
#pragma unroll
                for (int k = 0; k < 64; k += 4) {
                    float4 a = *(const float4*)&xq[i * 64 + k];
                    float4 c = *(const float4*)&xk[j * 64 + k];
                    s += a.x * c.x + a.y * c.y + a.z * c.z + a.w * c.w;
                }
            }
            At[t] = s;
        }
        __syncthreads();

        // ---- grad = ln_fused_l2_bwd
        {
#pragma unroll
            for (int rr = 0; rr < 2; rr++) {
                int i = (wp << 1) + rr;
                float z0 = Zb[i * 64 + lane], z1 = Zb[i * 64 + lane + 32];
                float s = z0 + z1, s2 = z0 * z0 + z1 * z1;
#pragma unroll
                for (int off = 16; off; off >>= 1) {
                    s  += __shfl_xor_sync(0xffffffffu, s,  off);
                    s2 += __shfl_xor_sync(0xffffffffu, s2, off);
                }
                float mu = s * (1.f / 64.f);
                float var = s2 * (1.f / 64.f) - mu * mu;
                float std = sqrtf(var + 1e-6f);
                float rstd = 1.f / std;
                float xh0 = (z0 - mu) * rstd, xh1 = (z1 - mu) * rstd;
                float g0 = gam[lane], g1 = gam[lane + 32];
                float gx0 = (g0 * xh0 + bet[lane]      - (xv[i * 64 + lane]      - xk[i * 64 + lane]))      * g0;
                float gx1 = (g1 * xh1 + bet[lane + 32] - (xv[i * 64 + lane + 32] - xk[i * 64 + lane + 32])) * g1;
                float sg = gx0 + gx1, sx = gx0 * xh0 + gx1 * xh1;
#pragma unroll
                for (int off = 16; off; off >>= 1) {
                    sg += __shfl_xor_sync(0xffffffffu, sg, off);
                    sx += __shfl_xor_sync(0xffffffffu, sx, off);
                }
                float cc = 1.f / (64.f * std);
                G[i * 64 + lane]      = (64.f * gx0 - sg - xh0 * sx) * cc;
                G[i * 64 + lane + 32] = (64.f * gx1 - sg - xh1 * sx) * cc;
            }
        }
        __syncthreads();

        // ---- Z1_bar
        {
            float ti0 = tki[i0], ti1 = tki[i0 + 1], ti2 = tki[i0 + 2], ti3 = tki[i0 + 3];
            float a0 = b1[d], a1 = a0, a2 = a0, a3 = a0;
#pragma unroll
            for (int j = 0; j < 16; j++) {
                float bbx = lrs[j] * G[j * 64 + d];
                if (j <= i0)     a0 -= ti0 * bbx * (1.f + At[(i0 + 0) * 16 + j]);
                if (j <= i0 + 1) a1 -= ti1 * bbx * (1.f + At[(i0 + 1) * 16 + j]);
                if (j <= i0 + 2) a2 -= ti2 * bbx * (1.f + At[(i0 + 2) * 16 + j]);
                if (j <= i0 + 3) a3 -= ti3 * bbx * (1.f + At[(i0 + 3) * 16 + j]);
            }
#pragma unroll
            for (int k4 = 0; k4 < 64; k4 += 4) {
                float4 x0 = *(const float4*)&xq[(i0 + 0) * 64 + k4];
                float4 x1 = *(const float4*)&xq[(i0 + 1) * 64 + k4];
                float4 x2 = *(const float4*)&xq[(i0 + 2) * 64 + k4];
                float4 x3 = *(const float4*)&xq[(i0 + 3) * 64 + k4];
                float w0 = W1[(k4 + 0) * 64 + d], w1 = W1[(k4 + 1) * 64 + d];
                float w2 = W1[(k4 + 2) * 64 + d], w3 = W1[(k4 + 3) * 64 + d];
                a0 += x0.x * w0 + x0.y * w1 + x0.z * w2 + x0.w * w3;
                a1 += x1.x * w0 + x1.y * w1 + x1.z * w2 + x1.w * w3;
                a2 += x2.x * w0 + x2.y * w1 + x2.z * w2 + x2.w * w3;
                a3 += x3.x * w0 + x3.y * w1 + x3.z * w2 + x3.w * w3;
            }
            Zb[(i0 + 0) * 64 + d] = a0; Zb[(i0 + 1) * 64 + d] = a1;
            Zb[(i0 + 2) * 64 + d] = a2; Zb[(i0 + 3) * 64 + d] = a3;
        }
        __syncthreads();

        // ---- W1/b1 update  AND  out = xq + LN(Z1_bar)
        {
            float te = tki[15];
            float ge[16];
#pragma unroll
            for (int k = 0; k < 16; k++) ge[k] = lrs[k] * G[k * 64 + d];
            float acc[16];
#pragma unroll
            for (int s_ = 0; s_ < 16; s_++) acc[s_] = 0.f;
#pragma unroll
            for (int k = 0; k < 16; k++) {
                const float4* xr = (const float4*)&xk[k * 64 + (g << 4)];
                float4 x0 = xr[0], x1 = xr[1], x2 = xr[2], x3 = xr[3];
                float gg = ge[k];
                acc[0]  += x0.x * gg; acc[1]  += x0.y * gg; acc[2]  += x0.z * gg; acc[3]  += x0.w * gg;
                acc[4]  += x1.x * gg; acc[5]  += x1.y * gg; acc[6]  += x1.z * gg; acc[7]  += x1.w * gg;
                acc[8]  += x2.x * gg; acc[9]  += x2.y * gg; acc[10] += x2.z * gg; acc[11] += x2.w * gg;
                acc[12] += x3.x * gg; acc[13] += x3.y * gg; acc[14] += x3.z * gg; acc[15] += x3.w * gg;
            }
#pragma unroll
            for (int s_ = 0; s_ < 16; s_++) {
                int dd = (g << 4) + s_;
                W1[dd * 64 + d] -= te * acc[s_];
            }
            if (g == 0) {
                float sb = 0.f;
#pragma unroll
                for (int k = 0; k < 16; k++) sb += ge[k];
                b1[d] -= te * sb;
            }

#pragma unroll
            for (int rr = 0; rr < 2; rr++) {
                int i = (wp << 1) + rr;
                float z0 = Zb[i * 64 + lane], z1 = Zb[i * 64 + lane + 32];
                float s = z0 + z1, s2 = z0 * z0 + z1 * z1;
#pragma unroll
                for (int off = 16; off; off >>= 1) {
                    s  += __shfl_xor_sync(0xffffffffu, s,  off);
                    s2 += __shfl_xor_sync(0xffffffffu, s2, off);
                }
                float mu = s * (1.f / 64.f);
                float var = s2 * (1.f / 64.f) - mu * mu;
                float rs = rsqrtf(var + 1e-6f);
                float o0 = xq[i * 64 + lane]      + (z0 - mu) * rs * gam[lane]      + bet[lane];
                float o1 = xq[i * 64 + lane + 32] + (z1 - mu) * rs * gam[lane + 32] + bet[lane + 32];
                size_t row = (size_t)(b << 10) + (nc << 4) + i;
                g_to[row * 1024 + (h << 6) + lane]      = o0;
                g_to[row * 1024 + (h << 6) + lane + 32] = o1;
            }
        }
        __syncthreads();
    }
}

// ---------------- launch ----------------------------------------------------
extern "C" void kernel_launch(void* const* d_in, const int* in_sizes, int n_in,
                              void* d_out, int out_size) {
    (void)in_sizes; (void)n_in; (void)out_size;
    const float* x    = (const float*)d_in[0];
    const float* ln1w = (const float*)d_in[2];
    const float* ln1b = (const float*)d_in[3];
    const float* wq   = (const float*)d_in[4];
    const float* wk   = (const float*)d_in[5];
    const float* wv   = (const float*)d_in[6];
    const float* wo   = (const float*)d_in[7];
    const float* W1i  = (const float*)d_in[8];
    const float* b1i  = (const float*)d_in[9];
    const float* nw   = (const float*)d_in[10];
    const float* nb   = (const float*)d_in[11];
    const float* lrw  = (const float*)d_in[12];
    const float* lrb  = (const float*)d_in[13];
    const float* tokp = (const float*)d_in[14];
    const float* pnw  = (const float*)d_in[15];
    const float* pnb  = (const float*)d_in[16];
    const float* ln2w = (const float*)d_in[17];
    const float* ln2b = (const float*)d_in[18];
    const float* win  = (const float*)d_in[19];
    const float* bin  = (const float*)d_in[20];
    const float* wout = (const float*)d_in[21];
    const float* bout = (const float*)d_in[22];
    float* out = (float*)d_out;

    float *ph, *pq, *pk, *pv, *pt, *pm, *pw;
    cudaGetSymbolAddress((void**)&ph, g_h);
    cudaGetSymbolAddress((void**)&pq, g_q);
    cudaGetSymbolAddress((void**)&pk, g_k);
    cudaGetSymbolAddress((void**)&pv, g_v);
    cudaGetSymbolAddress((void**)&pt, g_to);
    cudaGetSymbolAddress((void**)&pm, g_mlp);
    cudaGetSymbolAddress((void**)&pw, g_wts);

    float* rwq = pw;
    float* rwk = pw + 1u*1024*1024;
    float* rwv = pw + 2u*1024*1024;
    float* rwo = pw + 3u*1024*1024;
    float* rwi = pw + 4u*1024*1024;
    float* rwu = pw + 8u*1024*1024;

    cudaFuncSetAttribute(gemm_tc<8>,  cudaFuncAttributeMaxDynamicSharedMemorySize, GEMM_SMEM);
    cudaFuncSetAttribute(gemm_tc<4>,  cudaFuncAttributeMaxDynamicSharedMemorySize, GEMM_SMEM);
    cudaFuncSetAttribute(gemm_tc<19>, cudaFuncAttributeMaxDynamicSharedMemorySize, GEMM_SMEM);
    cudaFuncSetAttribute(gemm_tc<5>,  cudaFuncAttributeMaxDynamicSharedMemorySize, GEMM_SMEM);

    dim3 g1(Dn / 256, Mn / 128);   // (4, 256)
    dim3 g2(In / 256, Mn / 128);   // (16, 256)

    // #1 h = LN(x) (rounded)
    ln_kernel<1><<<Mn / 8, 256>>>(x, ln1w, ln1b, ph, 1e-5f);
    // #2 ttt_lr
    lr_kernel<<<Mn, 256>>>(lrw, lrb);
    // #3 round wq
    round_kernel<<<1024, 256>>>(wq, rwq, 1024*1024/4);
    // #4 XQ gemm (profiled slot)
    gemm_tc<8><<<g1, 256, GEMM_SMEM>>>(ph, rwq, nullptr, nullptr, pq, Mn, Dn, Dn);
    round_kernel<<<1024, 256>>>(wk, rwk, 1024*1024/4);
    gemm_tc<8><<<g1, 256, GEMM_SMEM>>>(ph, rwk, nullptr, nullptr, pk, Mn, Dn, Dn);
    round_kernel<<<1024, 256>>>(wv, rwv, 1024*1024/4);
    gemm_tc<8><<<g1, 256, GEMM_SMEM>>>(ph, rwv, nullptr, nullptr, pv, Mn, Dn, Dn);
    round_kernel<<<1024, 256>>>(wo,   rwo, 1024*1024/4);
    round_kernel<<<4096, 256>>>(win,  rwi, 4*1024*1024/4);
    round_kernel<<<4096, 256>>>(wout, rwu, 4*1024*1024/4);
    ttt_scan_kernel<<<Bn * NHn, 256>>>(W1i, b1i, nw, nb, tokp);
    ln_kernel<1><<<Mn / 8, 256>>>(pt, pnw, pnb, ph, 1e-5f);
    gemm_tc<4><<<g1, 256, GEMM_SMEM>>>(ph, rwo, nullptr, x, pq, Mn, Dn, Dn);
    ln_kernel<1><<<Mn / 8, 256>>>(pq, ln2w, ln2b, pk, 1e-5f);
    gemm_tc<19><<<g2, 256, GEMM_SMEM>>>(pk, rwi, bin, nullptr, pm, Mn, In, Dn);
    gemm_tc<5><<<g1, 256, GEMM_SMEM>>>(pm, rwu, bout, pq, out, Mn, Dn, In);
}